// round 1
// baseline (speedup 1.0000x reference)
#include <cuda_runtime.h>

// SoftBCELoss fused kernel.
// input:  [B=?, C=2, T=60000] fp32 probabilities in [0.01, 0.99]
// target: same shape, binary {0,1} fp32
// output: 3 fp32 scalars: (total, total_beat, total_down)
//
// target_process collapses to a circular symmetric 7-tap conv:
//   w = {0:1.328125, +-1:0.65625, +-2:0.3125, +-3:0.125}, then min(.,1)
// alpha = gamma = 0.5 -> per-channel loss = 0.5 * sum(bce) / (B*T).

#define GRID   2048
#define NTHR   256
#define T4     15000   // T/4 float4 groups per row (T = 60000)

__device__ float2 g_block[GRID];

__global__ __launch_bounds__(NTHR)
void loss_main(const float4* __restrict__ inp,
               const float4* __restrict__ tgt,
               int n4)
{
    const float W0 = 1.328125f, W1 = 0.65625f, W2 = 0.3125f, W3 = 0.125f;
    float acc0 = 0.0f, acc1 = 0.0f;

    const int stride = GRID * NTHR;
    for (int g = blockIdx.x * NTHR + threadIdx.x; g < n4; g += stride) {
        const int row  = g / T4;
        const int rem  = g - row * T4;
        const int base = row * T4;

        float4 p4 = inp[g];
        float4 c4 = tgt[g];
        const int remM = (rem == 0)      ? (T4 - 1) : (rem - 1);
        const int remP = (rem == T4 - 1) ? 0        : (rem + 1);
        float4 m4 = tgt[base + remM];   // wraps circularly within the row
        float4 q4 = tgt[base + remP];

        // window tgt[t4-3 .. t4+6]
        const float w0 = m4.y, w1 = m4.z, w2 = m4.w;
        const float w3 = c4.x, w4 = c4.y, w5 = c4.z, w6 = c4.w;
        const float w7 = q4.x, w8 = q4.y, w9 = q4.z;

        const float s10 = ((w0 + w1) + (w2 + w3)) + ((w4 + w5) + (w6 + w7)) + (w8 + w9);
        const bool anyt = __any_sync(__activemask(), s10 > 0.0f);

        float pa0 = p4.x, pa1 = p4.y, pa2 = p4.z, pa3 = p4.w;
        float ls = 0.0f;

        if (anyt) {
            float t0 = fminf(W3 * (w0 + w6) + W2 * (w1 + w5) + W1 * (w2 + w4) + W0 * w3, 1.0f);
            float t1 = fminf(W3 * (w1 + w7) + W2 * (w2 + w6) + W1 * (w3 + w5) + W0 * w4, 1.0f);
            float t2 = fminf(W3 * (w2 + w8) + W2 * (w3 + w7) + W1 * (w4 + w6) + W0 * w5, 1.0f);
            float t3 = fminf(W3 * (w3 + w9) + W2 * (w4 + w8) + W1 * (w5 + w7) + W0 * w6, 1.0f);

            float pv[4] = {pa0, pa1, pa2, pa3};
            float tv[4] = {t0, t1, t2, t3};
            #pragma unroll
            for (int i = 0; i < 4; i++) {
                float p  = pv[i];
                float l0 = fmaxf(__logf(1.0f - p), -100.0f);  // log1p(-p)
                float l1 = fmaxf(__logf(p),        -100.0f);  // log(p)
                // -(t*l1 + (1-t)*l0) == -(l0 + t*(l1-l0))
                ls -= l0 + tv[i] * (l1 - l0);
            }
        } else {
            // all 4 t_aug values are exactly 0 for every lane in the warp
            float pv[4] = {pa0, pa1, pa2, pa3};
            #pragma unroll
            for (int i = 0; i < 4; i++)
                ls -= fmaxf(__logf(1.0f - pv[i]), -100.0f);
        }

        if (row & 1) acc1 += ls; else acc0 += ls;
    }

    // warp reduce
    #pragma unroll
    for (int o = 16; o > 0; o >>= 1) {
        acc0 += __shfl_xor_sync(0xffffffffu, acc0, o);
        acc1 += __shfl_xor_sync(0xffffffffu, acc1, o);
    }
    __shared__ float s0[NTHR / 32], s1[NTHR / 32];
    const int lane = threadIdx.x & 31, wid = threadIdx.x >> 5;
    if (lane == 0) { s0[wid] = acc0; s1[wid] = acc1; }
    __syncthreads();
    if (wid == 0) {
        float a = (lane < NTHR / 32) ? s0[lane] : 0.0f;
        float b = (lane < NTHR / 32) ? s1[lane] : 0.0f;
        #pragma unroll
        for (int o = 4; o > 0; o >>= 1) {
            a += __shfl_xor_sync(0xffffffffu, a, o);
            b += __shfl_xor_sync(0xffffffffu, b, o);
        }
        if (lane == 0) g_block[blockIdx.x] = make_float2(a, b);
    }
}

__global__ __launch_bounds__(NTHR)
void loss_final(float* __restrict__ out, long long num)
{
    __shared__ double sa[NTHR], sb[NTHR];
    double a = 0.0, b = 0.0;
    for (int i = threadIdx.x; i < GRID; i += NTHR) {
        float2 v = g_block[i];
        a += (double)v.x;
        b += (double)v.y;
    }
    sa[threadIdx.x] = a;
    sb[threadIdx.x] = b;
    __syncthreads();
    for (int o = NTHR / 2; o > 0; o >>= 1) {
        if (threadIdx.x < o) {
            sa[threadIdx.x] += sa[threadIdx.x + o];
            sb[threadIdx.x] += sb[threadIdx.x + o];
        }
        __syncthreads();
    }
    if (threadIdx.x == 0) {
        double dn = (double)num;
        float tb = (float)(0.5 * sa[0] / dn);
        float td = (float)(0.5 * sb[0] / dn);
        out[0] = tb + td;
        out[1] = tb;
        out[2] = td;
    }
}

extern "C" void kernel_launch(void* const* d_in, const int* in_sizes, int n_in,
                              void* d_out, int out_size)
{
    const float4* inp = (const float4*)d_in[0];
    const float4* tgt = (const float4*)d_in[1];
    const int n  = in_sizes[0];      // B*C*T = 30,720,000
    const int n4 = n / 4;            // float4 groups
    loss_main<<<GRID, NTHR>>>(inp, tgt, n4);
    loss_final<<<1, NTHR>>>((float*)d_out, (long long)(n / 2));  // num = B*T
}

// round 2
// speedup vs baseline: 1.0770x; 1.0770x over previous
#include <cuda_runtime.h>

// SoftBCELoss fused single-kernel.
// input:  [B, C=2, T=60000] fp32 probabilities in [0.01, 0.99]
// target: same shape, binary {0,1} fp32
// out:    3 fp32 scalars (total, total_beat, total_down)
//
// target_process == circular symmetric 7-tap conv
//   w = {0:1.328125, +-1:0.65625, +-2:0.3125, +-3:0.125}, then min(.,1)
// alpha = gamma = 0.5 -> per-channel loss = 0.5 * sum(bce) / (B*T)
//
// Grid: (BLK_X, rows) 2D; no integer division on the address path.
// Finalization done by the last-arriving block (atomic ticket), so the
// whole thing is ONE launch.

#define NTHR   256
#define BLK_X  4
#define T4     15000   // T/4 float4 groups per row (T = 60000)

__device__ float2       g_block[8192];   // partials, indexed row*BLK_X + bx
__device__ unsigned int g_count = 0;     // wraps back to 0 every full pass

__global__ __launch_bounds__(NTHR)
void loss_fused(const float4* __restrict__ inp,
                const float4* __restrict__ tgt,
                float* __restrict__ out,
                int n_rows)
{
    const float W0 = 1.328125f, W1 = 0.65625f, W2 = 0.3125f, W3 = 0.125f;

    const int row   = blockIdx.y;
    const int base  = row * T4;
    const int strideX = BLK_X * NTHR;

    float acc = 0.0f;

    for (int rem = blockIdx.x * NTHR + threadIdx.x; rem < T4; rem += strideX) {
        const int remM = (rem == 0)      ? (T4 - 1) : (rem - 1);
        const int remP = (rem == T4 - 1) ? 0        : (rem + 1);

        // all four loads have no arithmetic dependency -> full MLP
        float4 p4 = inp[base + rem];
        float4 c4 = tgt[base + rem];
        float4 m4 = tgt[base + remM];
        float4 q4 = tgt[base + remP];

        // window tgt[4*rem-3 .. 4*rem+6]
        const float w0 = m4.y, w1 = m4.z, w2 = m4.w;
        const float w3 = c4.x, w4 = c4.y, w5 = c4.z, w6 = c4.w;
        const float w7 = q4.x, w8 = q4.y, w9 = q4.z;

        const float s10 = ((w0 + w1) + (w2 + w3)) + ((w4 + w5) + (w6 + w7)) + (w8 + w9);
        const bool anyt = __any_sync(__activemask(), s10 > 0.0f);

        float ls = 0.0f;
        float pv[4] = {p4.x, p4.y, p4.z, p4.w};

        if (anyt) {
            float tv[4];
            tv[0] = fminf(W3 * (w0 + w6) + W2 * (w1 + w5) + W1 * (w2 + w4) + W0 * w3, 1.0f);
            tv[1] = fminf(W3 * (w1 + w7) + W2 * (w2 + w6) + W1 * (w3 + w5) + W0 * w4, 1.0f);
            tv[2] = fminf(W3 * (w2 + w8) + W2 * (w3 + w7) + W1 * (w4 + w6) + W0 * w5, 1.0f);
            tv[3] = fminf(W3 * (w3 + w9) + W2 * (w4 + w8) + W1 * (w5 + w7) + W0 * w6, 1.0f);
            #pragma unroll
            for (int i = 0; i < 4; i++) {
                float p  = pv[i];
                float l0 = fmaxf(__logf(1.0f - p), -100.0f);  // log(1-p)
                float l1 = fmaxf(__logf(p),        -100.0f);  // log(p)
                ls -= l0 + tv[i] * (l1 - l0);                  // -(t*l1+(1-t)*l0)
            }
        } else {
            // whole warp's window is zero -> t_aug == 0 exactly
            #pragma unroll
            for (int i = 0; i < 4; i++)
                ls -= fmaxf(__logf(1.0f - pv[i]), -100.0f);
        }
        acc += ls;
    }

    // block reduce
    #pragma unroll
    for (int o = 16; o > 0; o >>= 1)
        acc += __shfl_xor_sync(0xffffffffu, acc, o);

    __shared__ float swarp[NTHR / 32];
    const int lane = threadIdx.x & 31, wid = threadIdx.x >> 5;
    if (lane == 0) swarp[wid] = acc;
    __syncthreads();

    const int n_blocks = n_rows * BLK_X;

    __shared__ bool s_last;
    if (threadIdx.x == 0) {
        float a = 0.0f;
        #pragma unroll
        for (int i = 0; i < NTHR / 32; i++) a += swarp[i];
        // channel = row & 1 (rows are [B][C] with C=2)
        float2 v = (row & 1) ? make_float2(0.0f, a) : make_float2(a, 0.0f);
        g_block[row * BLK_X + blockIdx.x] = v;
        __threadfence();
        unsigned t = atomicInc(&g_count, (unsigned)(n_blocks - 1));
        s_last = (t == (unsigned)(n_blocks - 1));
    }
    __syncthreads();

    if (!s_last) return;

    // ---- last block: final deterministic reduction over all partials ----
    double a = 0.0, b = 0.0;
    for (int i = threadIdx.x; i < n_blocks; i += NTHR) {
        float2 v = g_block[i];
        a += (double)v.x;
        b += (double)v.y;
    }
    __shared__ double sa[NTHR], sb[NTHR];
    sa[threadIdx.x] = a;
    sb[threadIdx.x] = b;
    __syncthreads();
    for (int o = NTHR / 2; o > 0; o >>= 1) {
        if (threadIdx.x < o) {
            sa[threadIdx.x] += sa[threadIdx.x + o];
            sb[threadIdx.x] += sb[threadIdx.x + o];
        }
        __syncthreads();
    }
    if (threadIdx.x == 0) {
        double dn = (double)n_rows * 0.5 * (double)(4 * T4);  // num = B*T = rows/2 * T
        float tb = (float)(0.5 * sa[0] / dn);
        float td = (float)(0.5 * sb[0] / dn);
        out[0] = tb + td;
        out[1] = tb;
        out[2] = td;
    }
}

extern "C" void kernel_launch(void* const* d_in, const int* in_sizes, int n_in,
                              void* d_out, int out_size)
{
    const float4* inp = (const float4*)d_in[0];
    const float4* tgt = (const float4*)d_in[1];
    const int n      = in_sizes[0];          // B*C*T
    const int n_rows = n / (4 * T4);         // B*C (= 512 for B=256)
    dim3 grid(BLK_X, n_rows);
    loss_fused<<<grid, NTHR>>>(inp, tgt, (float*)d_out, n_rows);
}

// round 4
// speedup vs baseline: 1.0819x; 1.0046x over previous
#include <cuda_runtime.h>

// SoftBCELoss fused single-kernel, round 3 (resubmit after infra failure).
// input:  [B, C=2, T=60000] fp32 probabilities in [0.01, 0.99]
// target: same shape, binary {0,1} fp32
// out:    3 fp32 scalars (total, total_beat, total_down)
//
// target_process == circular symmetric 7-tap conv
//   w = {0:1.328125, +-1:0.65625, +-2:0.3125, +-3:0.125}, then min(.,1)
// alpha = gamma = 0.5 -> per-channel loss = 0.5 * sum(bce) / (B*T)
//
// BCE accumulated in log2 domain (bare MUFU.LG2, ln2 applied once at the
// end). p in [0.01,0.99] makes the -100 clips dead code. 8 elems/thread
// (two adjacent float4s) amortizes the 2-load halo. One launch: the last
// arriving block does the final deterministic reduction.

#define NTHR   256
#define BLK_X  4
#define T4     15000           // float4 groups per row (T = 60000)
#define J2     (T4 / 2)        // 7500 float4-pairs per row

__device__ float2       g_block[8192];   // partials, row*BLK_X + bx (log2 units)
__device__ unsigned int g_count = 0;     // wraps to 0 every full pass

__global__ __launch_bounds__(NTHR)
void loss_fused(const float4* __restrict__ inp,
                const float4* __restrict__ tgt,
                float* __restrict__ out,
                int n_rows)
{
    const float W0 = 1.328125f, W1 = 0.65625f, W2 = 0.3125f, W3 = 0.125f;

    const int row     = blockIdx.y;
    const int base    = row * T4;
    const int strideX = BLK_X * NTHR;

    float acc = 0.0f;   // sum of (lg0 + t*(lg1-lg0)) in log2 units (negative)

    for (int j = blockIdx.x * NTHR + threadIdx.x; j < J2; j += strideX) {
        const int g     = 2 * j;
        const int gPrev = (j == 0)      ? (T4 - 1) : (g - 1);
        const int gNext = (j == J2 - 1) ? 0        : (g + 2);

        // 6 independent 128-bit loads, no arithmetic on the address path
        const float4 i0 = inp[base + g];
        const float4 i1 = inp[base + g + 1];
        const float4 c0 = tgt[base + g];
        const float4 c1 = tgt[base + g + 1];
        const float4 pm = tgt[base + gPrev];
        const float4 pn = tgt[base + gNext];

        // window tgt[8j-3 .. 8j+10] -> w[0..13]
        const float w0 = pm.y, w1 = pm.z, w2 = pm.w;
        const float w3 = c0.x, w4 = c0.y, w5 = c0.z, w6 = c0.w;
        const float w7 = c1.x, w8 = c1.y, w9 = c1.z, w10 = c1.w;
        const float w11 = pn.x, w12 = pn.y, w13 = pn.z;

        float tv[8];
        tv[0] = fminf(W0*w3  + W1*(w2+w4)  + W2*(w1+w5)  + W3*(w0+w6),  1.0f);
        tv[1] = fminf(W0*w4  + W1*(w3+w5)  + W2*(w2+w6)  + W3*(w1+w7),  1.0f);
        tv[2] = fminf(W0*w5  + W1*(w4+w6)  + W2*(w3+w7)  + W3*(w2+w8),  1.0f);
        tv[3] = fminf(W0*w6  + W1*(w5+w7)  + W2*(w4+w8)  + W3*(w3+w9),  1.0f);
        tv[4] = fminf(W0*w7  + W1*(w6+w8)  + W2*(w5+w9)  + W3*(w4+w10), 1.0f);
        tv[5] = fminf(W0*w8  + W1*(w7+w9)  + W2*(w6+w10) + W3*(w5+w11), 1.0f);
        tv[6] = fminf(W0*w9  + W1*(w8+w10) + W2*(w7+w11) + W3*(w6+w12), 1.0f);
        tv[7] = fminf(W0*w10 + W1*(w9+w11) + W2*(w8+w12) + W3*(w7+w13), 1.0f);

        const float pv[8] = {i0.x, i0.y, i0.z, i0.w, i1.x, i1.y, i1.z, i1.w};

        #pragma unroll
        for (int k = 0; k < 8; k++) {
            const float p   = pv[k];
            const float lg0 = __log2f(1.0f - p);   // bare MUFU.LG2
            const float lg1 = __log2f(p);
            // bce = -ln2 * (lg0 + t*(lg1-lg0)); accumulate without ln2
            acc += lg0 + tv[k] * (lg1 - lg0);
        }
    }

    // block reduce (still log2 units)
    #pragma unroll
    for (int o = 16; o > 0; o >>= 1)
        acc += __shfl_xor_sync(0xffffffffu, acc, o);

    __shared__ float swarp[NTHR / 32];
    const int lane = threadIdx.x & 31, wid = threadIdx.x >> 5;
    if (lane == 0) swarp[wid] = acc;
    __syncthreads();

    const int n_blocks = n_rows * BLK_X;

    __shared__ bool s_last;
    if (threadIdx.x == 0) {
        float a = 0.0f;
        #pragma unroll
        for (int i = 0; i < NTHR / 32; i++) a += swarp[i];
        // channel = row & 1 (rows are [B][C], C = 2)
        float2 v = (row & 1) ? make_float2(0.0f, a) : make_float2(a, 0.0f);
        g_block[row * BLK_X + blockIdx.x] = v;
        __threadfence();
        unsigned t = atomicInc(&g_count, (unsigned)(n_blocks - 1));
        s_last = (t == (unsigned)(n_blocks - 1));
    }
    __syncthreads();

    if (!s_last) return;

    // ---- last block: deterministic final reduction ----
    double a = 0.0, b = 0.0;
    for (int i = threadIdx.x; i < n_blocks; i += NTHR) {
        float2 v = g_block[i];
        a += (double)v.x;
        b += (double)v.y;
    }
    __shared__ double sa[NTHR], sb[NTHR];
    sa[threadIdx.x] = a;
    sb[threadIdx.x] = b;
    __syncthreads();
    for (int o = NTHR / 2; o > 0; o >>= 1) {
        if (threadIdx.x < o) {
            sa[threadIdx.x] += sa[threadIdx.x + o];
            sb[threadIdx.x] += sb[threadIdx.x + o];
        }
        __syncthreads();
    }
    if (threadIdx.x == 0) {
        const double LN2 = 0.6931471805599453;
        double dn = (double)n_rows * 0.5 * (double)(4 * T4);  // num = B*T
        // bce sums are -LN2 * (log2-domain sums)
        float tb = (float)(-0.5 * LN2 * sa[0] / dn);
        float td = (float)(-0.5 * LN2 * sb[0] / dn);
        out[0] = tb + td;
        out[1] = tb;
        out[2] = td;
    }
}

extern "C" void kernel_launch(void* const* d_in, const int* in_sizes, int n_in,
                              void* d_out, int out_size)
{
    const float4* inp = (const float4*)d_in[0];
    const float4* tgt = (const float4*)d_in[1];
    const int n      = in_sizes[0];          // B*C*T
    const int n_rows = n / (4 * T4);         // B*C (512 for B=256)
    dim3 grid(BLK_X, n_rows);
    loss_fused<<<grid, NTHR>>>(inp, tgt, (float*)d_out, n_rows);
}